// round 5
// baseline (speedup 1.0000x reference)
#include <cuda_runtime.h>
#include <math.h>

// ===========================================================================
// Mamba3ScanBlock — N=65536, D_MODEL=8, D_INNER=16, D_STATE=16
//
// K0 prep : fused projections -> g_dtxb (dt,xb), g_B, g_C, g_zx (silu(z), D*xb)
// K1 scan : chunked parallel scan (CHUNK=32 + WARM=40 contraction warm-up,
//           2048 chunks = 2048 warps). 1 warp = 1 chunk: 2 lanes/channel,
//           8 states/lane, f32x2 packed math, B/C loaded pre-packed as u64
//           pairs, 1 roll-SHFL + 1 reduce-SHFL per step. Warp-private fused
//           output-projection epilogue.
//           FIX vs r4: t_begin clamped to 0 (CHUNK < WARM made chunk 1's
//           warm-up start negative); h0 loaded whenever t_begin == 0.
// ===========================================================================

#define MAXN   65536
#define CHUNK  32
#define WARM   40
#define WPB    4      // warps (=chunks) per block

__device__ __align__(16) float2 g_dtxb[MAXN * 16];  // (dt, xb) per (t,ch)
__device__ __align__(16) float  g_B   [MAXN * 16];
__device__ __align__(16) float  g_C   [MAXN * 16];
__device__ __align__(16) float2 g_zx  [MAXN * 16];  // (silu(z), D*xb) per (t,ch)

// ---------------- f32x2 packed helpers -------------------------------------
typedef unsigned long long u64p;

__device__ __forceinline__ u64p pk2(float lo, float hi) {
    u64p r;
    unsigned int a = __float_as_uint(lo), b = __float_as_uint(hi);
    asm("mov.b64 %0, {%1, %2};" : "=l"(r) : "r"(a), "r"(b));
    return r;
}
__device__ __forceinline__ float plo(u64p v) {
    unsigned int a, b;
    asm("mov.b64 {%0, %1}, %2;" : "=r"(a), "=r"(b) : "l"(v));
    return __uint_as_float(a);
}
__device__ __forceinline__ float phi(u64p v) {
    unsigned int a, b;
    asm("mov.b64 {%0, %1}, %2;" : "=r"(a), "=r"(b) : "l"(v));
    return __uint_as_float(b);
}
__device__ __forceinline__ u64p fma2(u64p a, u64p b, u64p c) {
    u64p d; asm("fma.rn.f32x2 %0, %1, %2, %3;" : "=l"(d) : "l"(a), "l"(b), "l"(c));
    return d;
}
__device__ __forceinline__ u64p mul2(u64p a, u64p b) {
    u64p d; asm("mul.rn.f32x2 %0, %1, %2;" : "=l"(d) : "l"(a), "l"(b));
    return d;
}
__device__ __forceinline__ float frcp(float x) {
    float r; asm("rcp.approx.f32 %0, %1;" : "=f"(r) : "f"(x));
    return r;
}
__device__ __forceinline__ u64p rcp2(u64p a) {
    return pk2(frcp(plo(a)), frcp(phi(a)));
}

// ---------------------------------------------------------------------------
// K0: prep — 2 timesteps per thread, weights staged in smem (broadcast LDS)
// ---------------------------------------------------------------------------
__global__ void __launch_bounds__(256)
prep_kernel(const float* __restrict__ x,      // (N,8)
            const float* __restrict__ in_w,   // (32,8)
            const float* __restrict__ dt_w,   // (16,16)
            const float* __restrict__ dt_b,   // (16,)
            const float* __restrict__ B_w,    // (16,16)
            const float* __restrict__ C_w,    // (16,16)
            const float* __restrict__ Dp,     // (16,)
            int N)
{
    __shared__ float s_in[256], s_dt[256], s_B[256], s_C[256], s_b[16], s_D[16];
    int tid = threadIdx.x;
    s_in[tid] = in_w[tid];
    s_dt[tid] = dt_w[tid];
    s_B[tid]  = B_w[tid];
    s_C[tid]  = C_w[tid];
    if (tid < 16) { s_b[tid] = dt_b[tid]; s_D[tid] = Dp[tid]; }
    __syncthreads();

    int gid = blockIdx.x * 256 + tid;
    int t0 = gid * 2;
    if (t0 >= N) return;
    int t1 = (t0 + 1 < N) ? t0 + 1 : t0;

    float4 xa0 = __ldg((const float4*)(x + (size_t)t0 * 8));
    float4 xb0 = __ldg((const float4*)(x + (size_t)t0 * 8 + 4));
    float4 xa1 = __ldg((const float4*)(x + (size_t)t1 * 8));
    float4 xb1 = __ldg((const float4*)(x + (size_t)t1 * 8 + 4));

    float v0[16], v1[16];
    #pragma unroll
    for (int m = 0; m < 16; m++) {
        float4 wa = ((const float4*)s_in)[2 * m];
        float4 wb = ((const float4*)s_in)[2 * m + 1];
        v0[m] = fmaf(wa.x, xa0.x, fmaf(wa.y, xa0.y, fmaf(wa.z, xa0.z, fmaf(wa.w, xa0.w,
                fmaf(wb.x, xb0.x, fmaf(wb.y, xb0.y, fmaf(wb.z, xb0.z, wb.w * xb0.w)))))));
        v1[m] = fmaf(wa.x, xa1.x, fmaf(wa.y, xa1.y, fmaf(wa.z, xa1.z, fmaf(wa.w, xa1.w,
                fmaf(wb.x, xb1.x, fmaf(wb.y, xb1.y, fmaf(wb.z, xb1.z, wb.w * xb1.w)))))));
    }

    size_t base0 = (size_t)t0 * 16, base1 = (size_t)t1 * 16;

    #pragma unroll
    for (int m = 0; m < 16; m += 2) {
        float z[2][2];
        #pragma unroll
        for (int mm = 0; mm < 2; mm++) {
            float4 wa = ((const float4*)s_in)[32 + 2 * (m + mm)];
            float4 wb = ((const float4*)s_in)[33 + 2 * (m + mm)];
            z[mm][0] = fmaf(wa.x, xa0.x, fmaf(wa.y, xa0.y, fmaf(wa.z, xa0.z, fmaf(wa.w, xa0.w,
                       fmaf(wb.x, xb0.x, fmaf(wb.y, xb0.y, fmaf(wb.z, xb0.z, wb.w * xb0.w)))))));
            z[mm][1] = fmaf(wa.x, xa1.x, fmaf(wa.y, xa1.y, fmaf(wa.z, xa1.z, fmaf(wa.w, xa1.w,
                       fmaf(wb.x, xb1.x, fmaf(wb.y, xb1.y, fmaf(wb.z, xb1.z, wb.w * xb1.w)))))));
        }
        float zs00 = z[0][0] * frcp(1.0f + __expf(-z[0][0]));
        float zs10 = z[1][0] * frcp(1.0f + __expf(-z[1][0]));
        float zs01 = z[0][1] * frcp(1.0f + __expf(-z[0][1]));
        float zs11 = z[1][1] * frcp(1.0f + __expf(-z[1][1]));
        *((float4*)(g_zx + base0 + m)) = make_float4(zs00, s_D[m] * v0[m], zs10, s_D[m+1] * v0[m+1]);
        *((float4*)(g_zx + base1 + m)) = make_float4(zs01, s_D[m] * v1[m], zs11, s_D[m+1] * v1[m+1]);
    }

    #pragma unroll
    for (int i = 0; i < 16; i += 2) {
        float a00 = s_b[i], a01 = s_b[i], a10 = s_b[i+1], a11 = s_b[i+1];
        #pragma unroll
        for (int q = 0; q < 4; q++) {
            float4 w0 = ((const float4*)s_dt)[i * 4 + q];
            float4 w1 = ((const float4*)s_dt)[(i + 1) * 4 + q];
            a00 = fmaf(w0.x, v0[4*q], fmaf(w0.y, v0[4*q+1], fmaf(w0.z, v0[4*q+2], fmaf(w0.w, v0[4*q+3], a00))));
            a01 = fmaf(w0.x, v1[4*q], fmaf(w0.y, v1[4*q+1], fmaf(w0.z, v1[4*q+2], fmaf(w0.w, v1[4*q+3], a01))));
            a10 = fmaf(w1.x, v0[4*q], fmaf(w1.y, v0[4*q+1], fmaf(w1.z, v0[4*q+2], fmaf(w1.w, v0[4*q+3], a10))));
            a11 = fmaf(w1.x, v1[4*q], fmaf(w1.y, v1[4*q+1], fmaf(w1.z, v1[4*q+2], fmaf(w1.w, v1[4*q+3], a11))));
        }
        float d00 = (a00 > 15.0f) ? a00 : __logf(1.0f + __expf(a00));
        float d01 = (a01 > 15.0f) ? a01 : __logf(1.0f + __expf(a01));
        float d10 = (a10 > 15.0f) ? a10 : __logf(1.0f + __expf(a10));
        float d11 = (a11 > 15.0f) ? a11 : __logf(1.0f + __expf(a11));
        *((float4*)(g_dtxb + base0 + i)) = make_float4(d00, v0[i], d10, v0[i+1]);
        *((float4*)(g_dtxb + base1 + i)) = make_float4(d01, v1[i], d11, v1[i+1]);
    }

    #pragma unroll
    for (int j = 0; j < 16; j += 4) {
        float b0[4], b1[4], c0[4], c1[4];
        #pragma unroll
        for (int r = 0; r < 4; r++) {
            float bb0 = 0.f, bb1 = 0.f, cc0 = 0.f, cc1 = 0.f;
            #pragma unroll
            for (int q = 0; q < 4; q++) {
                float4 wB = ((const float4*)s_B)[(j + r) * 4 + q];
                float4 wC = ((const float4*)s_C)[(j + r) * 4 + q];
                bb0 = fmaf(wB.x, v0[4*q], fmaf(wB.y, v0[4*q+1], fmaf(wB.z, v0[4*q+2], fmaf(wB.w, v0[4*q+3], bb0))));
                bb1 = fmaf(wB.x, v1[4*q], fmaf(wB.y, v1[4*q+1], fmaf(wB.z, v1[4*q+2], fmaf(wB.w, v1[4*q+3], bb1))));
                cc0 = fmaf(wC.x, v0[4*q], fmaf(wC.y, v0[4*q+1], fmaf(wC.z, v0[4*q+2], fmaf(wC.w, v0[4*q+3], cc0))));
                cc1 = fmaf(wC.x, v1[4*q], fmaf(wC.y, v1[4*q+1], fmaf(wC.z, v1[4*q+2], fmaf(wC.w, v1[4*q+3], cc1))));
            }
            b0[r] = bb0; b1[r] = bb1; c0[r] = cc0; c1[r] = cc1;
        }
        *((float4*)(g_B + base0 + j)) = make_float4(b0[0], b0[1], b0[2], b0[3]);
        *((float4*)(g_B + base1 + j)) = make_float4(b1[0], b1[1], b1[2], b1[3]);
        *((float4*)(g_C + base0 + j)) = make_float4(c0[0], c0[1], c0[2], c0[3]);
        *((float4*)(g_C + base1 + j)) = make_float4(c1[0], c1[1], c1[2], c1[3]);
    }
}

// ---------------------------------------------------------------------------
// K1: scan + fused output projection. 1 warp = 1 chunk.
//   lane: ch = lane>>1, p = lane&1, states j = 8p..8p+7 (4 f32x2 pairs).
//   roll(h,1): shfl_xor of top element + in-register pair shift.
//   y = <C,h>: in-lane packed dot + 1 shfl_xor.
// ---------------------------------------------------------------------------
__global__ void __launch_bounds__(32 * WPB)
scan_kernel(const float* __restrict__ A_log,
            const float* __restrict__ rf,
            const float* __restrict__ h0,
            const float* __restrict__ ow,     // (8,16)
            float* __restrict__ d_out,
            int N, int nchunks, int write_hfinal)
{
    __shared__ float sy[WPB][CHUNK * 17];
    __shared__ float sow[128];

    const int tid  = threadIdx.x;
    const int lane = tid & 31;
    const int w    = tid >> 5;
    sow[tid] = __ldg(ow + tid);
    __syncthreads();

    const int chunk = blockIdx.x * WPB + w;
    if (chunk >= nchunks) return;

    const int ch = lane >> 1;
    const int p  = lane & 1;
    const int cidx = ch * 16 + p * 8;

    // per-lane constants (8 states = 4 packed pairs)
    float4 av0 = __ldg((const float4*)(A_log + cidx));
    float4 av1 = __ldg((const float4*)(A_log + cidx + 4));
    float4 rv0 = __ldg((const float4*)(rf + cidx));
    float4 rv1 = __ldg((const float4*)(rf + cidx + 4));
    const u64p Ah0 = pk2(-0.5f * __expf(av0.x), -0.5f * __expf(av0.y));
    const u64p Ah1 = pk2(-0.5f * __expf(av0.z), -0.5f * __expf(av0.w));
    const u64p Ah2 = pk2(-0.5f * __expf(av1.x), -0.5f * __expf(av1.y));
    const u64p Ah3 = pk2(-0.5f * __expf(av1.z), -0.5f * __expf(av1.w));
    const u64p Rf0 = pk2(rv0.x, rv0.y);
    const u64p Rf1 = pk2(rv0.z, rv0.w);
    const u64p Rf2 = pk2(rv1.x, rv1.y);
    const u64p Rf3 = pk2(rv1.z, rv1.w);
    const u64p ONE  = pk2(1.0f, 1.0f);
    const u64p NEG1 = pk2(-1.0f, -1.0f);
    const u64p TWO  = pk2(2.0f, 2.0f);
    const u64p K6   = pk2(1.0f/6.0f, 1.0f/6.0f);
    const u64p K24  = pk2(1.0f/24.0f, 1.0f/24.0f);
    const u64p Kn05 = pk2(-0.5f, -0.5f);

    const int t_main  = chunk * CHUNK;
    int t_begin = t_main - WARM;
    if (t_begin < 0) t_begin = 0;                  // FIX: clamp (CHUNK < WARM)
    int t_end = t_main + CHUNK; if (t_end > N) t_end = N;
    const int warmlen = t_main - t_begin;
    const int mainlen = t_end - t_main;

    u64p h0p, h1p, h2p, h3p;
    if (t_begin == 0) {                            // exact prefix: start from h0
        float4 a = __ldg((const float4*)(h0 + cidx));
        float4 b = __ldg((const float4*)(h0 + cidx + 4));
        h0p = pk2(a.x, a.y); h1p = pk2(a.z, a.w);
        h2p = pk2(b.x, b.y); h3p = pk2(b.z, b.w);
    } else {
        h0p = h1p = h2p = h3p = pk2(0.f, 0.f);
    }

    const float2*     pd = g_dtxb + (size_t)t_begin * 16 + ch;
    const ulonglong2* pB = (const ulonglong2*)g_B + (size_t)t_begin * 4 + 2 * p;
    const ulonglong2* pC = (const ulonglong2*)g_C + (size_t)t_begin * 4 + 2 * p;

    // ---- warm-up (no y) ----
    #pragma unroll 4
    for (int k = 0; k < warmlen; ++k) {
        float2     dx = __ldg(pd + (size_t)k * 16);
        ulonglong2 Bq = __ldg(pB + (size_t)k * 4);
        ulonglong2 Br = __ldg(pB + (size_t)k * 4 + 1);

        float dt = dx.x;
        u64p dtp = pk2(dt, dt);
        u64p u0 = mul2(dtp, Ah0), u1 = mul2(dtp, Ah1), u2 = mul2(dtp, Ah2), u3 = mul2(dtp, Ah3);
        u64p Ab0 = fma2(TWO, rcp2(fma2(u0, NEG1, ONE)), NEG1);
        u64p Ab1 = fma2(TWO, rcp2(fma2(u1, NEG1, ONE)), NEG1);
        u64p Ab2 = fma2(TWO, rcp2(fma2(u2, NEG1, ONE)), NEG1);
        u64p Ab3 = fma2(TWO, rcp2(fma2(u3, NEG1, ONE)), NEG1);
        u64p a0 = mul2(dtp, Rf0), a1 = mul2(dtp, Rf1), a2 = mul2(dtp, Rf2), a3 = mul2(dtp, Rf3);
        u64p q0 = mul2(a0, a0), q1 = mul2(a1, a1), q2 = mul2(a2, a2), q3 = mul2(a3, a3);
        u64p s0 = mul2(a0, fma2(q0, K6, NEG1));   // -sin
        u64p s1 = mul2(a1, fma2(q1, K6, NEG1));
        u64p s2 = mul2(a2, fma2(q2, K6, NEG1));
        u64p s3 = mul2(a3, fma2(q3, K6, NEG1));
        u64p c0 = fma2(q0, fma2(q0, K24, Kn05), ONE);
        u64p c1 = fma2(q1, fma2(q1, K24, Kn05), ONE);
        u64p c2 = fma2(q2, fma2(q2, K24, Kn05), ONE);
        u64p c3 = fma2(q3, fma2(q3, K24, Kn05), ONE);
        u64p Ac0 = mul2(Ab0, c0), Ac1 = mul2(Ab1, c1), Ac2 = mul2(Ab2, c2), Ac3 = mul2(Ab3, c3);
        u64p As0 = mul2(Ab0, s0), As1 = mul2(Ab1, s1), As2 = mul2(Ab2, s2), As3 = mul2(Ab3, s3);
        float db = dt * dx.y;
        u64p dbp = pk2(db, db);
        u64p bt0 = mul2(dbp, (u64p)Bq.x), bt1 = mul2(dbp, (u64p)Bq.y);
        u64p bt2 = mul2(dbp, (u64p)Br.x), bt3 = mul2(dbp, (u64p)Br.y);

        float prev = __shfl_xor_sync(0xffffffffu, phi(h3p), 1);
        u64p rp0 = pk2(prev,     plo(h0p));
        u64p rp1 = pk2(phi(h0p), plo(h1p));
        u64p rp2 = pk2(phi(h1p), plo(h2p));
        u64p rp3 = pk2(phi(h2p), plo(h3p));
        h0p = fma2(Ac0, h0p, fma2(As0, rp0, bt0));
        h1p = fma2(Ac1, h1p, fma2(As1, rp1, bt1));
        h2p = fma2(Ac2, h2p, fma2(As2, rp2, bt2));
        h3p = fma2(Ac3, h3p, fma2(As3, rp3, bt3));
    }

    // ---- main (update + y) ----
    #pragma unroll 4
    for (int m = 0; m < mainlen; ++m) {
        int k = warmlen + m;
        float2     dx = __ldg(pd + (size_t)k * 16);
        ulonglong2 Bq = __ldg(pB + (size_t)k * 4);
        ulonglong2 Br = __ldg(pB + (size_t)k * 4 + 1);
        ulonglong2 Cq = __ldg(pC + (size_t)k * 4);
        ulonglong2 Cr = __ldg(pC + (size_t)k * 4 + 1);

        float dt = dx.x;
        u64p dtp = pk2(dt, dt);
        u64p u0 = mul2(dtp, Ah0), u1 = mul2(dtp, Ah1), u2 = mul2(dtp, Ah2), u3 = mul2(dtp, Ah3);
        u64p Ab0 = fma2(TWO, rcp2(fma2(u0, NEG1, ONE)), NEG1);
        u64p Ab1 = fma2(TWO, rcp2(fma2(u1, NEG1, ONE)), NEG1);
        u64p Ab2 = fma2(TWO, rcp2(fma2(u2, NEG1, ONE)), NEG1);
        u64p Ab3 = fma2(TWO, rcp2(fma2(u3, NEG1, ONE)), NEG1);
        u64p a0 = mul2(dtp, Rf0), a1 = mul2(dtp, Rf1), a2 = mul2(dtp, Rf2), a3 = mul2(dtp, Rf3);
        u64p q0 = mul2(a0, a0), q1 = mul2(a1, a1), q2 = mul2(a2, a2), q3 = mul2(a3, a3);
        u64p s0 = mul2(a0, fma2(q0, K6, NEG1));
        u64p s1 = mul2(a1, fma2(q1, K6, NEG1));
        u64p s2 = mul2(a2, fma2(q2, K6, NEG1));
        u64p s3 = mul2(a3, fma2(q3, K6, NEG1));
        u64p c0 = fma2(q0, fma2(q0, K24, Kn05), ONE);
        u64p c1 = fma2(q1, fma2(q1, K24, Kn05), ONE);
        u64p c2 = fma2(q2, fma2(q2, K24, Kn05), ONE);
        u64p c3 = fma2(q3, fma2(q3, K24, Kn05), ONE);
        u64p Ac0 = mul2(Ab0, c0), Ac1 = mul2(Ab1, c1), Ac2 = mul2(Ab2, c2), Ac3 = mul2(Ab3, c3);
        u64p As0 = mul2(Ab0, s0), As1 = mul2(Ab1, s1), As2 = mul2(Ab2, s2), As3 = mul2(Ab3, s3);
        float db = dt * dx.y;
        u64p dbp = pk2(db, db);
        u64p bt0 = mul2(dbp, (u64p)Bq.x), bt1 = mul2(dbp, (u64p)Bq.y);
        u64p bt2 = mul2(dbp, (u64p)Br.x), bt3 = mul2(dbp, (u64p)Br.y);

        float prev = __shfl_xor_sync(0xffffffffu, phi(h3p), 1);
        u64p rp0 = pk2(prev,     plo(h0p));
        u64p rp1 = pk2(phi(h0p), plo(h1p));
        u64p rp2 = pk2(phi(h1p), plo(h2p));
        u64p rp3 = pk2(phi(h2p), plo(h3p));
        h0p = fma2(Ac0, h0p, fma2(As0, rp0, bt0));
        h1p = fma2(Ac1, h1p, fma2(As1, rp1, bt1));
        h2p = fma2(Ac2, h2p, fma2(As2, rp2, bt2));
        h3p = fma2(Ac3, h3p, fma2(As3, rp3, bt3));

        u64p yp = fma2((u64p)Cr.y, h3p, fma2((u64p)Cr.x, h2p,
                  fma2((u64p)Cq.y, h1p, mul2((u64p)Cq.x, h0p))));
        float y = plo(yp) + phi(yp);
        y += __shfl_xor_sync(0xffffffffu, y, 1);
        if (p == 0) sy[w][m * 17 + ch] = y;
    }

    // ---- final state ----
    if (write_hfinal && chunk == nchunks - 1) {
        float* o = d_out + (size_t)N * 8 + cidx;
        ((float4*)o)[0] = make_float4(plo(h0p), phi(h0p), plo(h1p), phi(h1p));
        ((float4*)o)[1] = make_float4(plo(h2p), phi(h2p), plo(h3p), phi(h3p));
    }

    __syncwarp();

    // ---- warp-private fused output projection ----
    if (lane < mainlen) {
        int t = t_main + lane;
        const float4* z4 = (const float4*)(g_zx + (size_t)t * 16);
        const float* syr = &sy[w][lane * 17];
        float v[16];
        #pragma unroll
        for (int q = 0; q < 4; q++) {
            float4 za = __ldg(z4 + 2 * q);
            float4 zb = __ldg(z4 + 2 * q + 1);
            v[4*q+0] = fmaf(syr[4*q+0], za.x, za.y);
            v[4*q+1] = fmaf(syr[4*q+1], za.z, za.w);
            v[4*q+2] = fmaf(syr[4*q+2], zb.x, zb.y);
            v[4*q+3] = fmaf(syr[4*q+3], zb.z, zb.w);
        }
        float o[8];
        #pragma unroll
        for (int d = 0; d < 8; d++) {
            float acc = 0.f;
            #pragma unroll
            for (int q = 0; q < 4; q++) {
                float4 wr = ((const float4*)sow)[d * 4 + q];
                acc = fmaf(wr.x, v[4*q+0], fmaf(wr.y, v[4*q+1],
                      fmaf(wr.z, v[4*q+2], fmaf(wr.w, v[4*q+3], acc))));
            }
            o[d] = acc;
        }
        ((float4*)(d_out + (size_t)t * 8))[0] = make_float4(o[0], o[1], o[2], o[3]);
        ((float4*)(d_out + (size_t)t * 8))[1] = make_float4(o[4], o[5], o[6], o[7]);
    }
}

// ---------------------------------------------------------------------------
extern "C" void kernel_launch(void* const* d_in, const int* in_sizes, int n_in,
                              void* d_out, int out_size)
{
    const float* x    = (const float*)d_in[0];
    const float* h0   = (const float*)d_in[1];
    const float* inw  = (const float*)d_in[2];
    const float* dtw  = (const float*)d_in[3];
    const float* dtb  = (const float*)d_in[4];
    const float* Bw   = (const float*)d_in[5];
    const float* Cw   = (const float*)d_in[6];
    const float* Alog = (const float*)d_in[7];
    const float* Dp   = (const float*)d_in[8];
    const float* rf   = (const float*)d_in[9];
    const float* ow   = (const float*)d_in[10];

    int N = in_sizes[0] / 8;
    if (N > MAXN) N = MAXN;
    int nchunks = (N + CHUNK - 1) / CHUNK;
    int write_hfinal = (out_size >= N * 8 + 256) ? 1 : 0;

    prep_kernel<<<(N / 2 + 255) / 256, 256>>>(x, inw, dtw, dtb, Bw, Cw, Dp, N);
    scan_kernel<<<(nchunks + WPB - 1) / WPB, 32 * WPB>>>(Alog, rf, h0, ow,
                                                         (float*)d_out, N, nchunks, write_hfinal);
}

// round 6
// speedup vs baseline: 1.0248x; 1.0248x over previous
#include <cuda_runtime.h>
#include <math.h>

// ===========================================================================
// Mamba3ScanBlock — N=65536, D_MODEL=8, D_INNER=16, D_STATE=16
//
// K0 prep : fused projections -> g_dtxb (dt,xb), g_B, g_C, g_zx (silu(z), D*xb)
// K1 scan : chunked parallel scan (CHUNK=32 + WARM=36). 1 warp = 1 chunk:
//           2 lanes/channel, 8 states/lane. Coefficient math f32x2-packed
//           (pre-packed constants, one pk2(dt,dt)/step); recurrence + y-dot
//           fully SCALAR (unpack of f32x2 halves is free, roll is register
//           indexing in descending order, 1 SHFL for the cross-lane wrap).
// ===========================================================================

#define MAXN   65536
#define CHUNK  32
#define WARM   36
#define WPB    4      // warps (=chunks) per block

__device__ __align__(16) float2 g_dtxb[MAXN * 16];  // (dt, xb) per (t,ch)
__device__ __align__(16) float  g_B   [MAXN * 16];
__device__ __align__(16) float  g_C   [MAXN * 16];
__device__ __align__(16) float2 g_zx  [MAXN * 16];  // (silu(z), D*xb) per (t,ch)

// ---------------- f32x2 packed helpers -------------------------------------
typedef unsigned long long u64p;

__device__ __forceinline__ u64p pk2(float lo, float hi) {
    u64p r;
    unsigned int a = __float_as_uint(lo), b = __float_as_uint(hi);
    asm("mov.b64 %0, {%1, %2};" : "=l"(r) : "r"(a), "r"(b));
    return r;
}
__device__ __forceinline__ float plo(u64p v) {
    unsigned int a, b;
    asm("mov.b64 {%0, %1}, %2;" : "=r"(a), "=r"(b) : "l"(v));
    return __uint_as_float(a);
}
__device__ __forceinline__ float phi(u64p v) {
    unsigned int a, b;
    asm("mov.b64 {%0, %1}, %2;" : "=r"(a), "=r"(b) : "l"(v));
    return __uint_as_float(b);
}
__device__ __forceinline__ u64p fma2(u64p a, u64p b, u64p c) {
    u64p d; asm("fma.rn.f32x2 %0, %1, %2, %3;" : "=l"(d) : "l"(a), "l"(b), "l"(c));
    return d;
}
__device__ __forceinline__ u64p mul2(u64p a, u64p b) {
    u64p d; asm("mul.rn.f32x2 %0, %1, %2;" : "=l"(d) : "l"(a), "l"(b));
    return d;
}
__device__ __forceinline__ float frcp(float x) {
    float r; asm("rcp.approx.f32 %0, %1;" : "=f"(r) : "f"(x));
    return r;
}

// ---------------------------------------------------------------------------
// K0: prep — 2 timesteps per thread, weights staged in smem (broadcast LDS)
// ---------------------------------------------------------------------------
__global__ void __launch_bounds__(256)
prep_kernel(const float* __restrict__ x,      // (N,8)
            const float* __restrict__ in_w,   // (32,8)
            const float* __restrict__ dt_w,   // (16,16)
            const float* __restrict__ dt_b,   // (16,)
            const float* __restrict__ B_w,    // (16,16)
            const float* __restrict__ C_w,    // (16,16)
            const float* __restrict__ Dp,     // (16,)
            int N)
{
    __shared__ float s_in[256], s_dt[256], s_B[256], s_C[256], s_b[16], s_D[16];
    int tid = threadIdx.x;
    s_in[tid] = in_w[tid];
    s_dt[tid] = dt_w[tid];
    s_B[tid]  = B_w[tid];
    s_C[tid]  = C_w[tid];
    if (tid < 16) { s_b[tid] = dt_b[tid]; s_D[tid] = Dp[tid]; }
    __syncthreads();

    int gid = blockIdx.x * 256 + tid;
    int t0 = gid * 2;
    if (t0 >= N) return;
    int t1 = (t0 + 1 < N) ? t0 + 1 : t0;

    float4 xa0 = __ldg((const float4*)(x + (size_t)t0 * 8));
    float4 xb0 = __ldg((const float4*)(x + (size_t)t0 * 8 + 4));
    float4 xa1 = __ldg((const float4*)(x + (size_t)t1 * 8));
    float4 xb1 = __ldg((const float4*)(x + (size_t)t1 * 8 + 4));

    float v0[16], v1[16];
    #pragma unroll
    for (int m = 0; m < 16; m++) {
        float4 wa = ((const float4*)s_in)[2 * m];
        float4 wb = ((const float4*)s_in)[2 * m + 1];
        v0[m] = fmaf(wa.x, xa0.x, fmaf(wa.y, xa0.y, fmaf(wa.z, xa0.z, fmaf(wa.w, xa0.w,
                fmaf(wb.x, xb0.x, fmaf(wb.y, xb0.y, fmaf(wb.z, xb0.z, wb.w * xb0.w)))))));
        v1[m] = fmaf(wa.x, xa1.x, fmaf(wa.y, xa1.y, fmaf(wa.z, xa1.z, fmaf(wa.w, xa1.w,
                fmaf(wb.x, xb1.x, fmaf(wb.y, xb1.y, fmaf(wb.z, xb1.z, wb.w * xb1.w)))))));
    }

    size_t base0 = (size_t)t0 * 16, base1 = (size_t)t1 * 16;

    #pragma unroll
    for (int m = 0; m < 16; m += 2) {
        float z[2][2];
        #pragma unroll
        for (int mm = 0; mm < 2; mm++) {
            float4 wa = ((const float4*)s_in)[32 + 2 * (m + mm)];
            float4 wb = ((const float4*)s_in)[33 + 2 * (m + mm)];
            z[mm][0] = fmaf(wa.x, xa0.x, fmaf(wa.y, xa0.y, fmaf(wa.z, xa0.z, fmaf(wa.w, xa0.w,
                       fmaf(wb.x, xb0.x, fmaf(wb.y, xb0.y, fmaf(wb.z, xb0.z, wb.w * xb0.w)))))));
            z[mm][1] = fmaf(wa.x, xa1.x, fmaf(wa.y, xa1.y, fmaf(wa.z, xa1.z, fmaf(wa.w, xa1.w,
                       fmaf(wb.x, xb1.x, fmaf(wb.y, xb1.y, fmaf(wb.z, xb1.z, wb.w * xb1.w)))))));
        }
        float zs00 = z[0][0] * frcp(1.0f + __expf(-z[0][0]));
        float zs10 = z[1][0] * frcp(1.0f + __expf(-z[1][0]));
        float zs01 = z[0][1] * frcp(1.0f + __expf(-z[0][1]));
        float zs11 = z[1][1] * frcp(1.0f + __expf(-z[1][1]));
        *((float4*)(g_zx + base0 + m)) = make_float4(zs00, s_D[m] * v0[m], zs10, s_D[m+1] * v0[m+1]);
        *((float4*)(g_zx + base1 + m)) = make_float4(zs01, s_D[m] * v1[m], zs11, s_D[m+1] * v1[m+1]);
    }

    #pragma unroll
    for (int i = 0; i < 16; i += 2) {
        float a00 = s_b[i], a01 = s_b[i], a10 = s_b[i+1], a11 = s_b[i+1];
        #pragma unroll
        for (int q = 0; q < 4; q++) {
            float4 w0 = ((const float4*)s_dt)[i * 4 + q];
            float4 w1 = ((const float4*)s_dt)[(i + 1) * 4 + q];
            a00 = fmaf(w0.x, v0[4*q], fmaf(w0.y, v0[4*q+1], fmaf(w0.z, v0[4*q+2], fmaf(w0.w, v0[4*q+3], a00))));
            a01 = fmaf(w0.x, v1[4*q], fmaf(w0.y, v1[4*q+1], fmaf(w0.z, v1[4*q+2], fmaf(w0.w, v1[4*q+3], a01))));
            a10 = fmaf(w1.x, v0[4*q], fmaf(w1.y, v0[4*q+1], fmaf(w1.z, v0[4*q+2], fmaf(w1.w, v0[4*q+3], a10))));
            a11 = fmaf(w1.x, v1[4*q], fmaf(w1.y, v1[4*q+1], fmaf(w1.z, v1[4*q+2], fmaf(w1.w, v1[4*q+3], a11))));
        }
        float d00 = (a00 > 15.0f) ? a00 : __logf(1.0f + __expf(a00));
        float d01 = (a01 > 15.0f) ? a01 : __logf(1.0f + __expf(a01));
        float d10 = (a10 > 15.0f) ? a10 : __logf(1.0f + __expf(a10));
        float d11 = (a11 > 15.0f) ? a11 : __logf(1.0f + __expf(a11));
        *((float4*)(g_dtxb + base0 + i)) = make_float4(d00, v0[i], d10, v0[i+1]);
        *((float4*)(g_dtxb + base1 + i)) = make_float4(d01, v1[i], d11, v1[i+1]);
    }

    #pragma unroll
    for (int j = 0; j < 16; j += 4) {
        float b0[4], b1[4], c0[4], c1[4];
        #pragma unroll
        for (int r = 0; r < 4; r++) {
            float bb0 = 0.f, bb1 = 0.f, cc0 = 0.f, cc1 = 0.f;
            #pragma unroll
            for (int q = 0; q < 4; q++) {
                float4 wB = ((const float4*)s_B)[(j + r) * 4 + q];
                float4 wC = ((const float4*)s_C)[(j + r) * 4 + q];
                bb0 = fmaf(wB.x, v0[4*q], fmaf(wB.y, v0[4*q+1], fmaf(wB.z, v0[4*q+2], fmaf(wB.w, v0[4*q+3], bb0))));
                bb1 = fmaf(wB.x, v1[4*q], fmaf(wB.y, v1[4*q+1], fmaf(wB.z, v1[4*q+2], fmaf(wB.w, v1[4*q+3], bb1))));
                cc0 = fmaf(wC.x, v0[4*q], fmaf(wC.y, v0[4*q+1], fmaf(wC.z, v0[4*q+2], fmaf(wC.w, v0[4*q+3], cc0))));
                cc1 = fmaf(wC.x, v1[4*q], fmaf(wC.y, v1[4*q+1], fmaf(wC.z, v1[4*q+2], fmaf(wC.w, v1[4*q+3], cc1))));
            }
            b0[r] = bb0; b1[r] = bb1; c0[r] = cc0; c1[r] = cc1;
        }
        *((float4*)(g_B + base0 + j)) = make_float4(b0[0], b0[1], b0[2], b0[3]);
        *((float4*)(g_B + base1 + j)) = make_float4(b1[0], b1[1], b1[2], b1[3]);
        *((float4*)(g_C + base0 + j)) = make_float4(c0[0], c0[1], c0[2], c0[3]);
        *((float4*)(g_C + base1 + j)) = make_float4(c1[0], c1[1], c1[2], c1[3]);
    }
}

// ---------------------------------------------------------------------------
// one scan step: packed coefficients, scalar recurrence
// ---------------------------------------------------------------------------
struct LaneConst {
    u64p Ah[4];   // A/2 packed pairs
    u64p Rf[4];   // rope freq packed pairs
};

#define STEP_COEFFS(dx, B0, B1)                                               \
    const float dt = dx.x;                                                    \
    const u64p dtp = pk2(dt, dt);                                             \
    u64p Ac[4], As[4];                                                        \
    _Pragma("unroll")                                                         \
    for (int q = 0; q < 4; q++) {                                             \
        u64p u  = mul2(dtp, lc.Ah[q]);                                        \
        u64p om = fma2(u, NEG1, ONE);           /* 1 - u */                   \
        u64p rp = pk2(frcp(plo(om)), frcp(phi(om)));                          \
        u64p Ab = fma2(TWO, rp, NEG1);          /* (1+u)/(1-u) */             \
        u64p a  = mul2(dtp, lc.Rf[q]);                                        \
        u64p qq = mul2(a, a);                                                 \
        u64p sn = mul2(a, fma2(qq, K6, NEG1));  /* -sin */                    \
        u64p cs = fma2(qq, fma2(qq, K24, Kn05), ONE);                         \
        Ac[q] = mul2(Ab, cs);                                                 \
        As[q] = mul2(Ab, sn);                                                 \
    }                                                                         \
    const float db = dt * dx.y;                                               \
    float bt[8];                                                              \
    bt[0] = db * B0.x; bt[1] = db * B0.y; bt[2] = db * B0.z; bt[3] = db * B0.w; \
    bt[4] = db * B1.x; bt[5] = db * B1.y; bt[6] = db * B1.z; bt[7] = db * B1.w; \
    const float wrap = __shfl_xor_sync(0xffffffffu, h[7], 1);                 \
    /* descending: h[j-1] still old when used */                             \
    h[7] = fmaf(phi(Ac[3]), h[7], fmaf(phi(As[3]), h[6], bt[7]));             \
    h[6] = fmaf(plo(Ac[3]), h[6], fmaf(plo(As[3]), h[5], bt[6]));             \
    h[5] = fmaf(phi(Ac[2]), h[5], fmaf(phi(As[2]), h[4], bt[5]));             \
    h[4] = fmaf(plo(Ac[2]), h[4], fmaf(plo(As[2]), h[3], bt[4]));             \
    h[3] = fmaf(phi(Ac[1]), h[3], fmaf(phi(As[1]), h[2], bt[3]));             \
    h[2] = fmaf(plo(Ac[1]), h[2], fmaf(plo(As[1]), h[1], bt[2]));             \
    h[1] = fmaf(phi(Ac[0]), h[1], fmaf(phi(As[0]), h[0], bt[1]));             \
    h[0] = fmaf(plo(Ac[0]), h[0], fmaf(plo(As[0]), wrap, bt[0]));

// ---------------------------------------------------------------------------
// K1: scan + fused output projection. 1 warp = 1 chunk.
// ---------------------------------------------------------------------------
__global__ void __launch_bounds__(32 * WPB)
scan_kernel(const float* __restrict__ A_log,
            const float* __restrict__ rf,
            const float* __restrict__ h0,
            const float* __restrict__ ow,     // (8,16)
            float* __restrict__ d_out,
            int N, int nchunks, int write_hfinal)
{
    __shared__ float sy[WPB][CHUNK * 17];
    __shared__ float sow[128];

    const int tid  = threadIdx.x;
    const int lane = tid & 31;
    const int w    = tid >> 5;
    sow[tid] = __ldg(ow + tid);
    __syncthreads();

    const int chunk = blockIdx.x * WPB + w;
    if (chunk >= nchunks) return;

    const int ch = lane >> 1;
    const int p  = lane & 1;
    const int cidx = ch * 16 + p * 8;

    LaneConst lc;
    {
        float4 av0 = __ldg((const float4*)(A_log + cidx));
        float4 av1 = __ldg((const float4*)(A_log + cidx + 4));
        float4 rv0 = __ldg((const float4*)(rf + cidx));
        float4 rv1 = __ldg((const float4*)(rf + cidx + 4));
        lc.Ah[0] = pk2(-0.5f * __expf(av0.x), -0.5f * __expf(av0.y));
        lc.Ah[1] = pk2(-0.5f * __expf(av0.z), -0.5f * __expf(av0.w));
        lc.Ah[2] = pk2(-0.5f * __expf(av1.x), -0.5f * __expf(av1.y));
        lc.Ah[3] = pk2(-0.5f * __expf(av1.z), -0.5f * __expf(av1.w));
        lc.Rf[0] = pk2(rv0.x, rv0.y);
        lc.Rf[1] = pk2(rv0.z, rv0.w);
        lc.Rf[2] = pk2(rv1.x, rv1.y);
        lc.Rf[3] = pk2(rv1.z, rv1.w);
    }
    const u64p ONE  = pk2(1.0f, 1.0f);
    const u64p NEG1 = pk2(-1.0f, -1.0f);
    const u64p TWO  = pk2(2.0f, 2.0f);
    const u64p K6   = pk2(1.0f/6.0f, 1.0f/6.0f);
    const u64p K24  = pk2(1.0f/24.0f, 1.0f/24.0f);
    const u64p Kn05 = pk2(-0.5f, -0.5f);

    const int t_main  = chunk * CHUNK;
    int t_begin = t_main - WARM;
    if (t_begin < 0) t_begin = 0;
    int t_end = t_main + CHUNK; if (t_end > N) t_end = N;
    const int warmlen = t_main - t_begin;
    const int mainlen = t_end - t_main;

    float h[8];
    if (t_begin == 0) {
        float4 a = __ldg((const float4*)(h0 + cidx));
        float4 b = __ldg((const float4*)(h0 + cidx + 4));
        h[0]=a.x; h[1]=a.y; h[2]=a.z; h[3]=a.w;
        h[4]=b.x; h[5]=b.y; h[6]=b.z; h[7]=b.w;
    } else {
        #pragma unroll
        for (int j = 0; j < 8; j++) h[j] = 0.f;
    }

    const float2* pd = g_dtxb + (size_t)t_begin * 16 + ch;
    const float4* pB = (const float4*)g_B + (size_t)t_begin * 4 + 2 * p;
    const float4* pC = (const float4*)g_C + (size_t)t_begin * 4 + 2 * p;

    // ---- warm-up (no y) ----
    #pragma unroll 4
    for (int k = 0; k < warmlen; ++k) {
        float2 dx = __ldg(pd + (size_t)k * 16);
        float4 B0 = __ldg(pB + (size_t)k * 4);
        float4 B1 = __ldg(pB + (size_t)k * 4 + 1);
        STEP_COEFFS(dx, B0, B1)
    }

    // ---- main (update + y) ----
    #pragma unroll 4
    for (int m = 0; m < mainlen; ++m) {
        int k = warmlen + m;
        float2 dx = __ldg(pd + (size_t)k * 16);
        float4 B0 = __ldg(pB + (size_t)k * 4);
        float4 B1 = __ldg(pB + (size_t)k * 4 + 1);
        float4 C0 = __ldg(pC + (size_t)k * 4);
        float4 C1 = __ldg(pC + (size_t)k * 4 + 1);
        STEP_COEFFS(dx, B0, B1)

        float y0 = C0.x * h[0];
        float y1 = C0.y * h[1];
        y0 = fmaf(C0.z, h[2], y0);
        y1 = fmaf(C0.w, h[3], y1);
        y0 = fmaf(C1.x, h[4], y0);
        y1 = fmaf(C1.y, h[5], y1);
        y0 = fmaf(C1.z, h[6], y0);
        y1 = fmaf(C1.w, h[7], y1);
        float y = y0 + y1;
        y += __shfl_xor_sync(0xffffffffu, y, 1);
        if (p == 0) sy[w][m * 17 + ch] = y;
    }

    // ---- final state ----
    if (write_hfinal && chunk == nchunks - 1) {
        float* o = d_out + (size_t)N * 8 + cidx;
        ((float4*)o)[0] = make_float4(h[0], h[1], h[2], h[3]);
        ((float4*)o)[1] = make_float4(h[4], h[5], h[6], h[7]);
    }

    __syncwarp();

    // ---- warp-private fused output projection ----
    if (lane < mainlen) {
        int t = t_main + lane;
        const float4* z4 = (const float4*)(g_zx + (size_t)t * 16);
        const float* syr = &sy[w][lane * 17];
        float v[16];
        #pragma unroll
        for (int q = 0; q < 4; q++) {
            float4 za = __ldg(z4 + 2 * q);
            float4 zb = __ldg(z4 + 2 * q + 1);
            v[4*q+0] = fmaf(syr[4*q+0], za.x, za.y);
            v[4*q+1] = fmaf(syr[4*q+1], za.z, za.w);
            v[4*q+2] = fmaf(syr[4*q+2], zb.x, zb.y);
            v[4*q+3] = fmaf(syr[4*q+3], zb.z, zb.w);
        }
        float o[8];
        #pragma unroll
        for (int d = 0; d < 8; d++) {
            float acc = 0.f;
            #pragma unroll
            for (int q = 0; q < 4; q++) {
                float4 wr = ((const float4*)sow)[d * 4 + q];
                acc = fmaf(wr.x, v[4*q+0], fmaf(wr.y, v[4*q+1],
                      fmaf(wr.z, v[4*q+2], fmaf(wr.w, v[4*q+3], acc))));
            }
            o[d] = acc;
        }
        ((float4*)(d_out + (size_t)t * 8))[0] = make_float4(o[0], o[1], o[2], o[3]);
        ((float4*)(d_out + (size_t)t * 8))[1] = make_float4(o[4], o[5], o[6], o[7]);
    }
}

// ---------------------------------------------------------------------------
extern "C" void kernel_launch(void* const* d_in, const int* in_sizes, int n_in,
                              void* d_out, int out_size)
{
    const float* x    = (const float*)d_in[0];
    const float* h0   = (const float*)d_in[1];
    const float* inw  = (const float*)d_in[2];
    const float* dtw  = (const float*)d_in[3];
    const float* dtb  = (const float*)d_in[4];
    const float* Bw   = (const float*)d_in[5];
    const float* Cw   = (const float*)d_in[6];
    const float* Alog = (const float*)d_in[7];
    const float* Dp   = (const float*)d_in[8];
    const float* rf   = (const float*)d_in[9];
    const float* ow   = (const float*)d_in[10];

    int N = in_sizes[0] / 8;
    if (N > MAXN) N = MAXN;
    int nchunks = (N + CHUNK - 1) / CHUNK;
    int write_hfinal = (out_size >= N * 8 + 256) ? 1 : 0;

    prep_kernel<<<(N / 2 + 255) / 256, 256>>>(x, inw, dtw, dtb, Bw, Cw, Dp, N);
    scan_kernel<<<(nchunks + WPB - 1) / WPB, 32 * WPB>>>(Alog, rf, h0, ow,
                                                         (float*)d_out, N, nchunks, write_hfinal);
}

// round 7
// speedup vs baseline: 1.3064x; 1.2748x over previous
#include <cuda_runtime.h>
#include <math.h>

// ===========================================================================
// Mamba3ScanBlock — N=65536, D_MODEL=8, D_INNER=16, D_STATE=16
//
// K0 prep : fused projections -> g_dtxb (dt, dt*xb), g_B, g_C, g_zx
// K1 scan : chunked parallel scan (CHUNK=32 + WARM=32). 1 warp = 1 chunk,
//           2 lanes/channel, 8 states/lane, packed-f32x2 coefficient math,
//           scalar recurrence. Inputs staged per-warp in SMEM tiles of 16
//           steps (8 batched LDG.128/lane -> STS; inner loop is LDS-only),
//           so gmem latency is amortized instead of exposed per step.
// ===========================================================================

#define MAXN   65536
#define CHUNK  32
#define WARM   32
#define WPB    4      // warps (=chunks) per block
#define TILE   16     // steps staged per warp at a time

__device__ __align__(16) float2 g_dtxb[MAXN * 16];  // (dt, dt*xb) per (t,ch)
__device__ __align__(16) float  g_B   [MAXN * 16];
__device__ __align__(16) float  g_C   [MAXN * 16];
__device__ __align__(16) float2 g_zx  [MAXN * 16];  // (silu(z), D*xb) per (t,ch)

// ---------------- f32x2 packed helpers -------------------------------------
typedef unsigned long long u64p;

__device__ __forceinline__ u64p pk2(float lo, float hi) {
    u64p r;
    unsigned int a = __float_as_uint(lo), b = __float_as_uint(hi);
    asm("mov.b64 %0, {%1, %2};" : "=l"(r) : "r"(a), "r"(b));
    return r;
}
__device__ __forceinline__ float plo(u64p v) {
    unsigned int a, b;
    asm("mov.b64 {%0, %1}, %2;" : "=r"(a), "=r"(b) : "l"(v));
    return __uint_as_float(a);
}
__device__ __forceinline__ float phi(u64p v) {
    unsigned int a, b;
    asm("mov.b64 {%0, %1}, %2;" : "=r"(a), "=r"(b) : "l"(v));
    return __uint_as_float(b);
}
__device__ __forceinline__ u64p fma2(u64p a, u64p b, u64p c) {
    u64p d; asm("fma.rn.f32x2 %0, %1, %2, %3;" : "=l"(d) : "l"(a), "l"(b), "l"(c));
    return d;
}
__device__ __forceinline__ u64p mul2(u64p a, u64p b) {
    u64p d; asm("mul.rn.f32x2 %0, %1, %2;" : "=l"(d) : "l"(a), "l"(b));
    return d;
}
__device__ __forceinline__ float frcp(float x) {
    float r; asm("rcp.approx.f32 %0, %1;" : "=f"(r) : "f"(x));
    return r;
}

// ---------------------------------------------------------------------------
// K0: prep — 2 timesteps per thread, weights staged in smem (broadcast LDS)
// ---------------------------------------------------------------------------
__global__ void __launch_bounds__(256)
prep_kernel(const float* __restrict__ x,      // (N,8)
            const float* __restrict__ in_w,   // (32,8)
            const float* __restrict__ dt_w,   // (16,16)
            const float* __restrict__ dt_b,   // (16,)
            const float* __restrict__ B_w,    // (16,16)
            const float* __restrict__ C_w,    // (16,16)
            const float* __restrict__ Dp,     // (16,)
            int N)
{
    __shared__ float s_in[256], s_dt[256], s_B[256], s_C[256], s_b[16], s_D[16];
    int tid = threadIdx.x;
    s_in[tid] = in_w[tid];
    s_dt[tid] = dt_w[tid];
    s_B[tid]  = B_w[tid];
    s_C[tid]  = C_w[tid];
    if (tid < 16) { s_b[tid] = dt_b[tid]; s_D[tid] = Dp[tid]; }
    __syncthreads();

    int gid = blockIdx.x * 256 + tid;
    int t0 = gid * 2;
    if (t0 >= N) return;
    int t1 = (t0 + 1 < N) ? t0 + 1 : t0;

    float4 xa0 = __ldg((const float4*)(x + (size_t)t0 * 8));
    float4 xb0 = __ldg((const float4*)(x + (size_t)t0 * 8 + 4));
    float4 xa1 = __ldg((const float4*)(x + (size_t)t1 * 8));
    float4 xb1 = __ldg((const float4*)(x + (size_t)t1 * 8 + 4));

    float v0[16], v1[16];
    #pragma unroll
    for (int m = 0; m < 16; m++) {
        float4 wa = ((const float4*)s_in)[2 * m];
        float4 wb = ((const float4*)s_in)[2 * m + 1];
        v0[m] = fmaf(wa.x, xa0.x, fmaf(wa.y, xa0.y, fmaf(wa.z, xa0.z, fmaf(wa.w, xa0.w,
                fmaf(wb.x, xb0.x, fmaf(wb.y, xb0.y, fmaf(wb.z, xb0.z, wb.w * xb0.w)))))));
        v1[m] = fmaf(wa.x, xa1.x, fmaf(wa.y, xa1.y, fmaf(wa.z, xa1.z, fmaf(wa.w, xa1.w,
                fmaf(wb.x, xb1.x, fmaf(wb.y, xb1.y, fmaf(wb.z, xb1.z, wb.w * xb1.w)))))));
    }

    size_t base0 = (size_t)t0 * 16, base1 = (size_t)t1 * 16;

    #pragma unroll
    for (int m = 0; m < 16; m += 2) {
        float z[2][2];
        #pragma unroll
        for (int mm = 0; mm < 2; mm++) {
            float4 wa = ((const float4*)s_in)[32 + 2 * (m + mm)];
            float4 wb = ((const float4*)s_in)[33 + 2 * (m + mm)];
            z[mm][0] = fmaf(wa.x, xa0.x, fmaf(wa.y, xa0.y, fmaf(wa.z, xa0.z, fmaf(wa.w, xa0.w,
                       fmaf(wb.x, xb0.x, fmaf(wb.y, xb0.y, fmaf(wb.z, xb0.z, wb.w * xb0.w)))))));
            z[mm][1] = fmaf(wa.x, xa1.x, fmaf(wa.y, xa1.y, fmaf(wa.z, xa1.z, fmaf(wa.w, xa1.w,
                       fmaf(wb.x, xb1.x, fmaf(wb.y, xb1.y, fmaf(wb.z, xb1.z, wb.w * xb1.w)))))));
        }
        float zs00 = z[0][0] * frcp(1.0f + __expf(-z[0][0]));
        float zs10 = z[1][0] * frcp(1.0f + __expf(-z[1][0]));
        float zs01 = z[0][1] * frcp(1.0f + __expf(-z[0][1]));
        float zs11 = z[1][1] * frcp(1.0f + __expf(-z[1][1]));
        *((float4*)(g_zx + base0 + m)) = make_float4(zs00, s_D[m] * v0[m], zs10, s_D[m+1] * v0[m+1]);
        *((float4*)(g_zx + base1 + m)) = make_float4(zs01, s_D[m] * v1[m], zs11, s_D[m+1] * v1[m+1]);
    }

    #pragma unroll
    for (int i = 0; i < 16; i += 2) {
        float a00 = s_b[i], a01 = s_b[i], a10 = s_b[i+1], a11 = s_b[i+1];
        #pragma unroll
        for (int q = 0; q < 4; q++) {
            float4 w0 = ((const float4*)s_dt)[i * 4 + q];
            float4 w1 = ((const float4*)s_dt)[(i + 1) * 4 + q];
            a00 = fmaf(w0.x, v0[4*q], fmaf(w0.y, v0[4*q+1], fmaf(w0.z, v0[4*q+2], fmaf(w0.w, v0[4*q+3], a00))));
            a01 = fmaf(w0.x, v1[4*q], fmaf(w0.y, v1[4*q+1], fmaf(w0.z, v1[4*q+2], fmaf(w0.w, v1[4*q+3], a01))));
            a10 = fmaf(w1.x, v0[4*q], fmaf(w1.y, v0[4*q+1], fmaf(w1.z, v0[4*q+2], fmaf(w1.w, v0[4*q+3], a10))));
            a11 = fmaf(w1.x, v1[4*q], fmaf(w1.y, v1[4*q+1], fmaf(w1.z, v1[4*q+2], fmaf(w1.w, v1[4*q+3], a11))));
        }
        float d00 = (a00 > 15.0f) ? a00 : __logf(1.0f + __expf(a00));
        float d01 = (a01 > 15.0f) ? a01 : __logf(1.0f + __expf(a01));
        float d10 = (a10 > 15.0f) ? a10 : __logf(1.0f + __expf(a10));
        float d11 = (a11 > 15.0f) ? a11 : __logf(1.0f + __expf(a11));
        // (dt, dt*xb) prefolded
        *((float4*)(g_dtxb + base0 + i)) = make_float4(d00, d00 * v0[i], d10, d10 * v0[i+1]);
        *((float4*)(g_dtxb + base1 + i)) = make_float4(d01, d01 * v1[i], d11, d11 * v1[i+1]);
    }

    #pragma unroll
    for (int j = 0; j < 16; j += 4) {
        float b0[4], b1[4], c0[4], c1[4];
        #pragma unroll
        for (int r = 0; r < 4; r++) {
            float bb0 = 0.f, bb1 = 0.f, cc0 = 0.f, cc1 = 0.f;
            #pragma unroll
            for (int q = 0; q < 4; q++) {
                float4 wB = ((const float4*)s_B)[(j + r) * 4 + q];
                float4 wC = ((const float4*)s_C)[(j + r) * 4 + q];
                bb0 = fmaf(wB.x, v0[4*q], fmaf(wB.y, v0[4*q+1], fmaf(wB.z, v0[4*q+2], fmaf(wB.w, v0[4*q+3], bb0))));
                bb1 = fmaf(wB.x, v1[4*q], fmaf(wB.y, v1[4*q+1], fmaf(wB.z, v1[4*q+2], fmaf(wB.w, v1[4*q+3], bb1))));
                cc0 = fmaf(wC.x, v0[4*q], fmaf(wC.y, v0[4*q+1], fmaf(wC.z, v0[4*q+2], fmaf(wC.w, v0[4*q+3], cc0))));
                cc1 = fmaf(wC.x, v1[4*q], fmaf(wC.y, v1[4*q+1], fmaf(wC.z, v1[4*q+2], fmaf(wC.w, v1[4*q+3], cc1))));
            }
            b0[r] = bb0; b1[r] = bb1; c0[r] = cc0; c1[r] = cc1;
        }
        *((float4*)(g_B + base0 + j)) = make_float4(b0[0], b0[1], b0[2], b0[3]);
        *((float4*)(g_B + base1 + j)) = make_float4(b1[0], b1[1], b1[2], b1[3]);
        *((float4*)(g_C + base0 + j)) = make_float4(c0[0], c0[1], c0[2], c0[3]);
        *((float4*)(g_C + base1 + j)) = make_float4(c1[0], c1[1], c1[2], c1[3]);
    }
}

// ---------------------------------------------------------------------------
// K1: scan + fused output projection. 1 warp = 1 chunk, SMEM-tile staged.
//   Tile record per step: float4[16] = [0:8) dtxb row, [8:12) B row, [12:16) C row.
// ---------------------------------------------------------------------------
struct LaneConst {
    u64p Ah[4];   // A/2 packed pairs
    u64p Rf[4];   // rope freq packed pairs
};

__global__ void __launch_bounds__(32 * WPB)
scan_kernel(const float* __restrict__ A_log,
            const float* __restrict__ rf,
            const float* __restrict__ h0,
            const float* __restrict__ ow,     // (8,16)
            float* __restrict__ d_out,
            int N, int nchunks, int write_hfinal)
{
    __shared__ float4 stile[WPB][TILE][16];
    __shared__ float  sy[WPB][CHUNK * 17];
    __shared__ float  sow[128];

    const int tid  = threadIdx.x;
    const int lane = tid & 31;
    const int w    = tid >> 5;
    sow[tid] = __ldg(ow + tid);
    __syncthreads();

    const int chunk = blockIdx.x * WPB + w;
    if (chunk >= nchunks) return;

    const int ch = lane >> 1;
    const int p  = lane & 1;
    const int cidx = ch * 16 + p * 8;

    LaneConst lc;
    {
        float4 av0 = __ldg((const float4*)(A_log + cidx));
        float4 av1 = __ldg((const float4*)(A_log + cidx + 4));
        float4 rv0 = __ldg((const float4*)(rf + cidx));
        float4 rv1 = __ldg((const float4*)(rf + cidx + 4));
        lc.Ah[0] = pk2(-0.5f * __expf(av0.x), -0.5f * __expf(av0.y));
        lc.Ah[1] = pk2(-0.5f * __expf(av0.z), -0.5f * __expf(av0.w));
        lc.Ah[2] = pk2(-0.5f * __expf(av1.x), -0.5f * __expf(av1.y));
        lc.Ah[3] = pk2(-0.5f * __expf(av1.z), -0.5f * __expf(av1.w));
        lc.Rf[0] = pk2(rv0.x, rv0.y);
        lc.Rf[1] = pk2(rv0.z, rv0.w);
        lc.Rf[2] = pk2(rv1.x, rv1.y);
        lc.Rf[3] = pk2(rv1.z, rv1.w);
    }
    const u64p ONE  = pk2(1.0f, 1.0f);
    const u64p NEG1 = pk2(-1.0f, -1.0f);
    const u64p TWO  = pk2(2.0f, 2.0f);
    const u64p K6   = pk2(1.0f/6.0f, 1.0f/6.0f);
    const u64p K24  = pk2(1.0f/24.0f, 1.0f/24.0f);
    const u64p Kn05 = pk2(-0.5f, -0.5f);

    const int t_main  = chunk * CHUNK;
    int t_begin = t_main - WARM;
    if (t_begin < 0) t_begin = 0;
    int t_end = t_main + CHUNK; if (t_end > N) t_end = N;
    const int warmlen = t_main - t_begin;      // 0 or 32 (tile-aligned)
    const int mainlen = t_end - t_main;

    float h[8];
    if (t_begin == 0) {
        float4 a = __ldg((const float4*)(h0 + cidx));
        float4 b = __ldg((const float4*)(h0 + cidx + 4));
        h[0]=a.x; h[1]=a.y; h[2]=a.z; h[3]=a.w;
        h[4]=b.x; h[5]=b.y; h[6]=b.z; h[7]=b.w;
    } else {
        #pragma unroll
        for (int j = 0; j < 8; j++) h[j] = 0.f;
    }

    float4 (*tile)[16] = stile[w];

    // stage TILE steps starting at absolute timestep t0 (cnt <= TILE)
    auto stage = [&](int t0, int cnt) {
        const float4* src_d = (const float4*)(g_dtxb + (size_t)t0 * 16); // 8/step
        const float4* src_B = (const float4*)(g_B    + (size_t)t0 * 16); // 4/step
        const float4* src_C = (const float4*)(g_C    + (size_t)t0 * 16); // 4/step
        __syncwarp();
        #pragma unroll
        for (int r = 0; r < 4; r++) {
            int idx = lane + 32 * r;                 // 0..127
            if (idx < cnt * 8) tile[idx >> 3][idx & 7] = __ldg(src_d + idx);
        }
        #pragma unroll
        for (int r = 0; r < 2; r++) {
            int idx = lane + 32 * r;                 // 0..63
            if (idx < cnt * 4) {
                tile[idx >> 2][8  + (idx & 3)] = __ldg(src_B + idx);
                tile[idx >> 2][12 + (idx & 3)] = __ldg(src_C + idx);
            }
        }
        __syncwarp();
    };

    // one recurrence step from tile record i (no y)
    auto step_h = [&](int i) {
        const float* rec = (const float*)tile[i];
        float2 dx = *(const float2*)(rec + ch * 2);
        float4 B0 = *(const float4*)(rec + 32 + p * 8);
        float4 B1 = *(const float4*)(rec + 36 + p * 8);
        const float dt = dx.x;
        const u64p dtp = pk2(dt, dt);
        u64p Ac[4], As[4];
        #pragma unroll
        for (int q = 0; q < 4; q++) {
            u64p u  = mul2(dtp, lc.Ah[q]);
            u64p om = fma2(u, NEG1, ONE);
            u64p rp = pk2(frcp(plo(om)), frcp(phi(om)));
            u64p Ab = fma2(TWO, rp, NEG1);
            u64p a  = mul2(dtp, lc.Rf[q]);
            u64p qq = mul2(a, a);
            u64p sn = mul2(a, fma2(qq, K6, NEG1));
            u64p cs = fma2(qq, fma2(qq, K24, Kn05), ONE);
            Ac[q] = mul2(Ab, cs);
            As[q] = mul2(Ab, sn);
        }
        const float db = dx.y;                      // dt*xb prefolded
        float bt[8];
        bt[0]=db*B0.x; bt[1]=db*B0.y; bt[2]=db*B0.z; bt[3]=db*B0.w;
        bt[4]=db*B1.x; bt[5]=db*B1.y; bt[6]=db*B1.z; bt[7]=db*B1.w;
        const float wrap = __shfl_xor_sync(0xffffffffu, h[7], 1);
        h[7] = fmaf(phi(Ac[3]), h[7], fmaf(phi(As[3]), h[6], bt[7]));
        h[6] = fmaf(plo(Ac[3]), h[6], fmaf(plo(As[3]), h[5], bt[6]));
        h[5] = fmaf(phi(Ac[2]), h[5], fmaf(phi(As[2]), h[4], bt[5]));
        h[4] = fmaf(plo(Ac[2]), h[4], fmaf(plo(As[2]), h[3], bt[4]));
        h[3] = fmaf(phi(Ac[1]), h[3], fmaf(phi(As[1]), h[2], bt[3]));
        h[2] = fmaf(plo(Ac[1]), h[2], fmaf(plo(As[1]), h[1], bt[2]));
        h[1] = fmaf(phi(Ac[0]), h[1], fmaf(phi(As[0]), h[0], bt[1]));
        h[0] = fmaf(plo(Ac[0]), h[0], fmaf(plo(As[0]), wrap, bt[0]));
    };

    // ---- warm-up tiles (no y) ----
    for (int k0 = 0; k0 < warmlen; k0 += TILE) {
        stage(t_begin + k0, TILE);
        #pragma unroll 4
        for (int i = 0; i < TILE; ++i) step_h(i);
    }

    // ---- main tiles (update + y) ----
    for (int m0 = 0; m0 < mainlen; m0 += TILE) {
        int cnt = mainlen - m0; if (cnt > TILE) cnt = TILE;
        stage(t_main + m0, cnt);
        #pragma unroll 4
        for (int i = 0; i < TILE; ++i) {
            if (i >= cnt) break;
            step_h(i);
            const float* rec = (const float*)tile[i];
            float4 C0 = *(const float4*)(rec + 48 + p * 8);
            float4 C1 = *(const float4*)(rec + 52 + p * 8);
            float y0 = C0.x * h[0];
            float y1 = C0.y * h[1];
            y0 = fmaf(C0.z, h[2], y0);
            y1 = fmaf(C0.w, h[3], y1);
            y0 = fmaf(C1.x, h[4], y0);
            y1 = fmaf(C1.y, h[5], y1);
            y0 = fmaf(C1.z, h[6], y0);
            y1 = fmaf(C1.w, h[7], y1);
            float y = y0 + y1;
            y += __shfl_xor_sync(0xffffffffu, y, 1);
            if (p == 0) sy[w][(m0 + i) * 17 + ch] = y;
        }
    }

    // ---- final state ----
    if (write_hfinal && chunk == nchunks - 1) {
        float* o = d_out + (size_t)N * 8 + cidx;
        ((float4*)o)[0] = make_float4(h[0], h[1], h[2], h[3]);
        ((float4*)o)[1] = make_float4(h[4], h[5], h[6], h[7]);
    }

    __syncwarp();

    // ---- warp-private fused output projection ----
    if (lane < mainlen) {
        int t = t_main + lane;
        const float4* z4 = (const float4*)(g_zx + (size_t)t * 16);
        const float* syr = &sy[w][lane * 17];
        float v[16];
        #pragma unroll
        for (int q = 0; q < 4; q++) {
            float4 za = __ldg(z4 + 2 * q);
            float4 zb = __ldg(z4 + 2 * q + 1);
            v[4*q+0] = fmaf(syr[4*q+0], za.x, za.y);
            v[4*q+1] = fmaf(syr[4*q+1], za.z, za.w);
            v[4*q+2] = fmaf(syr[4*q+2], zb.x, zb.y);
            v[4*q+3] = fmaf(syr[4*q+3], zb.z, zb.w);
        }
        float o[8];
        #pragma unroll
        for (int d = 0; d < 8; d++) {
            float acc = 0.f;
            #pragma unroll
            for (int q = 0; q < 4; q++) {
                float4 wr = ((const float4*)sow)[d * 4 + q];
                acc = fmaf(wr.x, v[4*q+0], fmaf(wr.y, v[4*q+1],
                      fmaf(wr.z, v[4*q+2], fmaf(wr.w, v[4*q+3], acc))));
            }
            o[d] = acc;
        }
        ((float4*)(d_out + (size_t)t * 8))[0] = make_float4(o[0], o[1], o[2], o[3]);
        ((float4*)(d_out + (size_t)t * 8))[1] = make_float4(o[4], o[5], o[6], o[7]);
    }
}

// ---------------------------------------------------------------------------
extern "C" void kernel_launch(void* const* d_in, const int* in_sizes, int n_in,
                              void* d_out, int out_size)
{
    const float* x    = (const float*)d_in[0];
    const float* h0   = (const float*)d_in[1];
    const float* inw  = (const float*)d_in[2];
    const float* dtw  = (const float*)d_in[3];
    const float* dtb  = (const float*)d_in[4];
    const float* Bw   = (const float*)d_in[5];
    const float* Cw   = (const float*)d_in[6];
    const float* Alog = (const float*)d_in[7];
    const float* Dp   = (const float*)d_in[8];
    const float* rf   = (const float*)d_in[9];
    const float* ow   = (const float*)d_in[10];

    int N = in_sizes[0] / 8;
    if (N > MAXN) N = MAXN;
    int nchunks = (N + CHUNK - 1) / CHUNK;
    int write_hfinal = (out_size >= N * 8 + 256) ? 1 : 0;

    prep_kernel<<<(N / 2 + 255) / 256, 256>>>(x, inw, dtw, dtb, Bw, Cw, Dp, N);
    scan_kernel<<<(nchunks + WPB - 1) / WPB, 32 * WPB>>>(Alog, rf, h0, ow,
                                                         (float*)d_out, N, nchunks, write_hfinal);
}